// round 5
// baseline (speedup 1.0000x reference)
#include <cuda_runtime.h>
#include <cstdint>

// PatchSampler: out[b,c,i,j] = bchw[b, c, iy[j], ix[i]], nearest = round-half-
// even of (center-16+k-0.5) = (center-16+k) & ~1, zero padding outside 1024^2.
//
// Round 5: launch-shape probe. Same scalar direct-gather body as the best
// measurement (6.656us, round 2), but 2048 CTAs x 128 threads: one bc per 8
// CTAs is wrong — one bc spans 8 CTAs (1024 outputs / 128 threads), so
// bc = blockIdx >> 3 is uniform per CTA and center loads stay broadcast.
// Many small CTAs pipeline through the work distributor and overlap the
// 2-hop latency chain at CTA granularity, shrinking the dispatch tail.

#define PS_C  128
#define PS_HW 1024
#define PS_R  16

__global__ __launch_bounds__(128, 16)
void patch_sampler_kernel(const float* __restrict__ bchw,
                          const int*   __restrict__ centers,
                          float*       __restrict__ out)
{
    const int blk = blockIdx.x;                // 0 .. 2047
    const int bc  = blk >> 3;                  // 0 .. 255, uniform per CTA
    const int b   = bc >> 7;
    const int c   = bc & 127;

    // hop 1: two independent broadcast LDGs, issued immediately
    const int cx = __ldg(&centers[b * (2 * PS_C) + c]);
    const int cy = __ldg(&centers[b * (2 * PS_C) + PS_C + c]);

    // overlaps hop-1 latency
    const int t = ((blk & 7) << 7) | threadIdx.x;   // 0 .. 1023 within patch
    const int i = t >> 5;                      // output dim 2 (x)
    const int j = t & 31;                      // output dim 3 (y), lane-fast
    float* __restrict__ dst = out + ((size_t)bc << 10) + t;
    const float* __restrict__ img = bchw + ((size_t)bc << 20);

    // round-half-even of (n - 0.5) for integer n = n & ~1
    const int ix = (cx - PS_R + i) & ~1;
    const int iy = (cy - PS_R + j) & ~1;

    // hop 2: gather (predicated, zero padding)
    float v = 0.0f;
    if ((unsigned)ix < (unsigned)PS_HW && (unsigned)iy < (unsigned)PS_HW)
        v = __ldg(img + ((size_t)iy << 10) + ix);

    *dst = v;                                  // coalesced 128B per warp
}

extern "C" void kernel_launch(void* const* d_in, const int* in_sizes, int n_in,
                              void* d_out, int out_size)
{
    const float* bchw    = (const float*)d_in[0];
    const int*   centers = (const int*)d_in[1];
    float*       out     = (float*)d_out;

    patch_sampler_kernel<<<2048, 128>>>(bchw, centers, out);
}

// round 6
// speedup vs baseline: 1.0435x; 1.0435x over previous
#include <cuda_runtime.h>
#include <cstdint>

// PatchSampler: out[b,c,i,j] = bchw[b, c, iy[j], ix[i]] with nearest rounding
// (round-half-even of (center - r + k - 0.5)), zero padding outside HxW.
//
// Shapes fixed by setup_inputs: B=2, C=128, H=W=1024, D=32, r=16.
// Coordinates are exact integers minus 0.5, so round-half-even gives
// ix = (cx - 16 + i) & ~1 (even-floor). Direct gather, no smem, no barrier:
// the 4x duplicated reads per address hit the same 32B sector (L1/L2
// coalesced), so there is no bandwidth problem to stage around.
//
// Final configuration: best-measured of 5 structurally distinct variants
// (6.656us). The problem is bounded below by a ~5us fixed per-launch floor
// (per-launch L1D flush + dispatch ramp); all throughput resources <2%.

#define PS_C  128
#define PS_HW 1024
#define PS_R  16

__global__ __launch_bounds__(1024, 2)
void patch_sampler_kernel(const float* __restrict__ bchw,
                          const int*   __restrict__ centers,
                          float*       __restrict__ out)
{
    const int bc = blockIdx.x;           // 0 .. B*C-1
    const int b  = bc >> 7;              // / 128
    const int c  = bc & 127;

    // hop 1: two independent broadcast LDGs, issued back-to-back
    const int cx = __ldg(&centers[b * (2 * PS_C) + c]);
    const int cy = __ldg(&centers[b * (2 * PS_C) + PS_C + c]);

    const int t = threadIdx.x;
    const int i = t >> 5;                // output dim 2 (x index)
    const int j = t & 31;                // output dim 3 (y index), lane-fast

    const int ix = (cx - PS_R + i) & ~1; // round-half-even of (n - 0.5)
    const int iy = (cy - PS_R + j) & ~1;

    // hop 2: predicated gather (zero padding outside the image)
    float v = 0.0f;
    if ((unsigned)ix < (unsigned)PS_HW && (unsigned)iy < (unsigned)PS_HW)
        v = __ldg(bchw + ((size_t)bc << 20) + ((size_t)iy << 10) + ix);

    out[((size_t)bc << 10) + t] = v;     // coalesced 128B per warp
}

extern "C" void kernel_launch(void* const* d_in, const int* in_sizes, int n_in,
                              void* d_out, int out_size)
{
    const float* bchw    = (const float*)d_in[0];
    const int*   centers = (const int*)d_in[1];
    float*       out     = (float*)d_out;

    patch_sampler_kernel<<<2 * PS_C, 1024>>>(bchw, centers, out);
}